// round 16
// baseline (speedup 1.0000x reference)
#include <cuda_runtime.h>
#include <cuda_bf16.h>
#include <cstdint>

// ---------------------------------------------------------------------------
// Problem constants
// ---------------------------------------------------------------------------
#define D_MODEL 2048
#define NHEADS  16
#define DHEAD   128
#define SEQ     2048
#define BATCH   2
#define MTOT    (BATCH * SEQ)        // 4096 rows
#define OUTSZ   (MTOT * D_MODEL)     // 8388608 elements per output tensor

// Scratch buffers (no cudaMalloc allowed -> device globals)
__device__ __nv_bfloat16 g_ahi[MTOT * D_MODEL];   // A-hi (x, then z)
__device__ __nv_bfloat16 g_alo[MTOT * D_MODEL];   // A-lo
__device__ __nv_bfloat16 g_bhi[3 * D_MODEL * D_MODEL]; // B-hi (Wqkv, then Wo)
__device__ __nv_bfloat16 g_blo[3 * D_MODEL * D_MODEL]; // B-lo
__device__ __nv_bfloat16 g_qhi[MTOT * D_MODEL];   // normalized q, hi/lo
__device__ __nv_bfloat16 g_qlo[MTOT * D_MODEL];
__device__ __nv_bfloat16 g_khi[MTOT * D_MODEL];   // normalized k, hi/lo
__device__ __nv_bfloat16 g_klo[MTOT * D_MODEL];
__device__ __nv_bfloat16 g_vhi[MTOT * D_MODEL];   // v, hi/lo
__device__ __nv_bfloat16 g_vlo[MTOT * D_MODEL];

typedef unsigned long long u64;

// ---------------------------------------------------------------------------
// Base-target tensor-core helpers (sm_80+ ISA: ldmatrix / mma.sync / cp.async)
// ---------------------------------------------------------------------------
__device__ __forceinline__ uint32_t smem_u32(const void* p) {
    uint32_t a;
    asm("{ .reg .u64 t; cvta.to.shared.u64 t, %1; cvt.u32.u64 %0, t; }"
        : "=r"(a) : "l"(p));
    return a;
}
__device__ __forceinline__ void ldsm_x4(uint32_t& r0, uint32_t& r1,
                                        uint32_t& r2, uint32_t& r3, uint32_t addr) {
    asm volatile("ldmatrix.sync.aligned.m8n8.x4.shared.b16 {%0,%1,%2,%3}, [%4];"
                 : "=r"(r0), "=r"(r1), "=r"(r2), "=r"(r3) : "r"(addr));
}
__device__ __forceinline__ void ldsm_x4_t(uint32_t& r0, uint32_t& r1,
                                          uint32_t& r2, uint32_t& r3, uint32_t addr) {
    asm volatile("ldmatrix.sync.aligned.m8n8.x4.trans.shared.b16 {%0,%1,%2,%3}, [%4];"
                 : "=r"(r0), "=r"(r1), "=r"(r2), "=r"(r3) : "r"(addr));
}
__device__ __forceinline__ void mma16816(float* d, const uint32_t* a,
                                         const uint32_t* b) {
    asm volatile("mma.sync.aligned.m16n8k16.row.col.f32.bf16.bf16.f32 "
                 "{%0,%1,%2,%3}, {%4,%5,%6,%7}, {%8,%9}, {%0,%1,%2,%3};"
                 : "+f"(d[0]), "+f"(d[1]), "+f"(d[2]), "+f"(d[3])
                 : "r"(a[0]), "r"(a[1]), "r"(a[2]), "r"(a[3]),
                   "r"(b[0]), "r"(b[1]));
}
__device__ __forceinline__ void cp_async16(uint32_t dst, const void* src) {
    asm volatile("cp.async.cg.shared.global [%0], [%1], 16;"
                 :: "r"(dst), "l"(src) : "memory");
}
__device__ __forceinline__ void cp_commit() {
    asm volatile("cp.async.commit_group;" ::: "memory");
}
template <int N>
__device__ __forceinline__ void cp_wait() {
    asm volatile("cp.async.wait_group %0;" :: "n"(N) : "memory");
}
// pack two fp32 -> bf16x2 (x -> low half, y -> high half), round-to-nearest
__device__ __forceinline__ uint32_t bf2pk(float x, float y) {
    uint32_t r;
    asm("cvt.rn.bf16x2.f32 %0, %1, %2;" : "=r"(r) : "f"(y), "f"(x));
    return r;
}
// split pair (p0,p1) into packed hi bf16x2 and packed lo bf16x2
__device__ __forceinline__ void split_pair(float p0, float p1,
                                           uint32_t& hpk, uint32_t& lpk) {
    hpk = bf2pk(p0, p1);
    float h0 = __uint_as_float(hpk << 16);
    float h1 = __uint_as_float(hpk & 0xffff0000u);
    lpk = bf2pk(p0 - h0, p1 - h1);
}

// ---------------------------------------------------------------------------
// fp32 -> (bf16 hi, bf16 lo) split, vectorized
// ---------------------------------------------------------------------------
__global__ __launch_bounds__(256)
void split_f32(const float* __restrict__ src, __nv_bfloat16* __restrict__ hi,
               __nv_bfloat16* __restrict__ lo, int n)
{
    int i = (blockIdx.x * 256 + threadIdx.x) * 4;
    if (i >= n) return;
    float4 x = *(const float4*)(src + i);
    uint32_t h01, l01, h23, l23;
    split_pair(x.x, x.y, h01, l01);
    split_pair(x.z, x.w, h23, l23);
    uint2 hv = {h01, h23}, lv = {l01, l23};
    *(uint2*)(hi + i) = hv;
    *(uint2*)(lo + i) = lv;
}

// ---------------------------------------------------------------------------
// HMMA (mma.sync) GEMM with bf16x3 fp32 emulation.
// mode 0: plain fp32 out (+bias) into out0 (segN width).
// mode 1: QKV-fused epilogue. Each 128-wide n-tile is exactly one head:
//   seg 0 (q): per-row RMSNorm (cross-warp ssq reduce) * wq -> qhi/qlo
//   seg 1 (k): fp32 k_new -> out1, RMSNorm * wk -> khi/klo
//   seg 2 (v): fp32 v_new -> out2, plain split -> vhi/vlo
// ---------------------------------------------------------------------------
#define GK    2048
#define BK2   32
#define APAD  40
#define PART_ELE (128 * APAD)
#define STAGE_B  (4 * PART_ELE * 2)
#define GEMM_SMEM (2 * STAGE_B)

__global__ __launch_bounds__(256, 2)
void gemm_mma(const __nv_bfloat16* __restrict__ Ahi, const __nv_bfloat16* __restrict__ Alo,
              const __nv_bfloat16* __restrict__ Bhi, const __nv_bfloat16* __restrict__ Blo,
              const float* __restrict__ bias,
              float* __restrict__ out0, float* __restrict__ out1,
              float* __restrict__ out2, int segN, int mode,
              const float* __restrict__ wq, const float* __restrict__ wk,
              __nv_bfloat16* __restrict__ qhi, __nv_bfloat16* __restrict__ qlo,
              __nv_bfloat16* __restrict__ khi, __nv_bfloat16* __restrict__ klo,
              __nv_bfloat16* __restrict__ vhi, __nv_bfloat16* __restrict__ vlo)
{
    extern __shared__ __align__(16) __nv_bfloat16 smem[];
    const uint32_t sb = smem_u32(smem);

    const int tid    = threadIdx.x;
    const int wid    = tid >> 5;
    const int lane   = tid & 31;
    const int warp_m = wid >> 2;
    const int warp_n = wid & 3;
    const int wm0    = warp_m * 64;
    const int wn0    = warp_n * 32;
    const int m0     = blockIdx.y * 128;
    const int n0     = blockIdx.x * 128;

    const __nv_bfloat16* gsrc[4];
    gsrc[0] = Ahi + (size_t)m0 * GK;
    gsrc[1] = Alo + (size_t)m0 * GK;
    gsrc[2] = Bhi + (size_t)n0 * GK;
    gsrc[3] = Blo + (size_t)n0 * GK;

    float acc[4][4][4];
#pragma unroll
    for (int mi = 0; mi < 4; mi++)
#pragma unroll
        for (int ni = 0; ni < 4; ni++)
#pragma unroll
            for (int e = 0; e < 4; e++) acc[mi][ni][e] = 0.f;

    auto load_tile = [&](int t, int buf) {
        const uint32_t sbase = sb + buf * STAGE_B;
#pragma unroll
        for (int p = 0; p < 4; p++) {
            const __nv_bfloat16* s = gsrc[p] + t * BK2;
            const uint32_t dbase = sbase + p * (PART_ELE * 2);
#pragma unroll
            for (int i = 0; i < 2; i++) {
                int idx = tid + i * 256;
                int r   = idx >> 2;
                int c   = (idx & 3) * 8;
                cp_async16(dbase + (r * APAD + c) * 2,
                           s + (size_t)r * GK + c);
            }
        }
        cp_commit();
    };

    load_tile(0, 0);

    const int ntiles = GK / BK2;
    for (int t = 0; t < ntiles; t++) {
        const int buf = t & 1;
        if (t + 1 < ntiles) load_tile(t + 1, buf ^ 1);
        if (t + 1 < ntiles) cp_wait<1>(); else cp_wait<0>();
        __syncthreads();

        const uint32_t aHiB = sb + buf * STAGE_B;
        const uint32_t aLoB = aHiB + PART_ELE * 2;
        const uint32_t bHiB = aHiB + 2 * PART_ELE * 2;
        const uint32_t bLoB = aHiB + 3 * PART_ELE * 2;

#pragma unroll
        for (int ks = 0; ks < 2; ks++) {
            const int brow = wn0 + ((lane >> 4) & 1) * 8 + (lane & 7);
            const int bkof = ks * 16 + ((lane >> 3) & 1) * 8;
            uint32_t bh[2][4], bl[2][4];
#pragma unroll
            for (int ni2 = 0; ni2 < 2; ni2++) {
                const uint32_t boff = ((brow + ni2 * 16) * APAD + bkof) * 2;
                ldsm_x4(bh[ni2][0], bh[ni2][1], bh[ni2][2], bh[ni2][3], bHiB + boff);
                ldsm_x4(bl[ni2][0], bl[ni2][1], bl[ni2][2], bl[ni2][3], bLoB + boff);
            }
            const int arow = wm0 + (lane & 15);
            const int akof = ks * 16 + (lane >> 4) * 8;
#pragma unroll
            for (int mi = 0; mi < 4; mi++) {
                const uint32_t aoff = ((arow + mi * 16) * APAD + akof) * 2;
                uint32_t ah[4], al[4];
                ldsm_x4(ah[0], ah[1], ah[2], ah[3], aHiB + aoff);
                ldsm_x4(al[0], al[1], al[2], al[3], aLoB + aoff);
#pragma unroll
                for (int ni = 0; ni < 4; ni++) {
                    const uint32_t* bhp = &bh[ni >> 1][(ni & 1) * 2];
                    const uint32_t* blp = &bl[ni >> 1][(ni & 1) * 2];
                    mma16816(acc[mi][ni], ah, bhp);
                    mma16816(acc[mi][ni], ah, blp);
                    mma16816(acc[mi][ni], al, bhp);
                }
            }
        }
        __syncthreads();
    }

    // ---- apply bias in-register ----
#pragma unroll
    for (int ni = 0; ni < 4; ni++) {
        const int gn = n0 + wn0 + ni * 8 + (lane & 3) * 2;
        float2 bv = *(const float2*)(bias + gn);
#pragma unroll
        for (int mi = 0; mi < 4; mi++) {
            acc[mi][ni][0] += bv.x; acc[mi][ni][1] += bv.y;
            acc[mi][ni][2] += bv.x; acc[mi][ni][3] += bv.y;
        }
    }

    const int seg = n0 / segN;

    if (mode == 0) {
        float* o = out0;
#pragma unroll
        for (int mi = 0; mi < 4; mi++) {
            const int gm = m0 + wm0 + mi * 16 + (lane >> 2);
#pragma unroll
            for (int ni = 0; ni < 4; ni++) {
                const int cn = n0 + wn0 + ni * 8 + (lane & 3) * 2;
                *(float2*)(o + (size_t)gm * segN + cn)       = *(float2*)&acc[mi][ni][0];
                *(float2*)(o + (size_t)(gm + 8) * segN + cn) = *(float2*)&acc[mi][ni][2];
            }
        }
        return;
    }

    // ---- fused QKV epilogue ----
    float* ssq = (float*)smem;   // [4 warp_n][128 rows]
    float rinv0[4], rinv1[4];

    if (seg < 2) {
        // per-row sum of squares: warp partial over its 32 cols
#pragma unroll
        for (int mi = 0; mi < 4; mi++) {
            float p0 = 0.f, p1 = 0.f;
#pragma unroll
            for (int ni = 0; ni < 4; ni++) {
                p0 += acc[mi][ni][0] * acc[mi][ni][0] + acc[mi][ni][1] * acc[mi][ni][1];
                p1 += acc[mi][ni][2] * acc[mi][ni][2] + acc[mi][ni][3] * acc[mi][ni][3];
            }
            p0 += __shfl_xor_sync(0xffffffffu, p0, 1);
            p0 += __shfl_xor_sync(0xffffffffu, p0, 2);
            p1 += __shfl_xor_sync(0xffffffffu, p1, 1);
            p1 += __shfl_xor_sync(0xffffffffu, p1, 2);
            if ((lane & 3) == 0) {
                const int rr = wm0 + mi * 16 + (lane >> 2);
                ssq[warp_n * 128 + rr]     = p0;
                ssq[warp_n * 128 + rr + 8] = p1;
            }
        }
        __syncthreads();
#pragma unroll
        for (int mi = 0; mi < 4; mi++) {
            const int rr = wm0 + mi * 16 + (lane >> 2);
            float t0 = ssq[rr] + ssq[128 + rr] + ssq[256 + rr] + ssq[384 + rr];
            float t1 = ssq[rr + 8] + ssq[128 + rr + 8] + ssq[256 + rr + 8] + ssq[384 + rr + 8];
            rinv0[mi] = rsqrtf(t0 * (1.0f / 128.0f) + 1e-6f);
            rinv1[mi] = rsqrtf(t1 * (1.0f / 128.0f) + 1e-6f);
        }
    }

    const int cn = (n0 - seg * segN) + wn0 + (lane & 3) * 2;  // col within 2048 seg
    const int hc = wn0 + (lane & 3) * 2;                      // col within head

#pragma unroll
    for (int mi = 0; mi < 4; mi++) {
        const int gm = m0 + wm0 + mi * 16 + (lane >> 2);
#pragma unroll
        for (int ni = 0; ni < 4; ni++) {
            const int col  = cn + ni * 8;
            const size_t i0 = (size_t)gm * segN + col;
            const size_t i1 = (size_t)(gm + 8) * segN + col;
            float a0 = acc[mi][ni][0], a1 = acc[mi][ni][1];
            float a2 = acc[mi][ni][2], a3 = acc[mi][ni][3];
            if (seg == 2) {
                *(float2*)(out2 + i0) = make_float2(a0, a1);
                *(float2*)(out2 + i1) = make_float2(a2, a3);
                uint32_t h, l;
                split_pair(a0, a1, h, l);
                *(uint32_t*)(vhi + i0) = h; *(uint32_t*)(vlo + i0) = l;
                split_pair(a2, a3, h, l);
                *(uint32_t*)(vhi + i1) = h; *(uint32_t*)(vlo + i1) = l;
            } else {
                const float* wn = (seg == 0) ? wq : wk;
                float2 wv = *(const float2*)(wn + hc + ni * 8);
                if (seg == 1) {
                    *(float2*)(out1 + i0) = make_float2(a0, a1);
                    *(float2*)(out1 + i1) = make_float2(a2, a3);
                }
                float y0 = a0 * rinv0[mi] * wv.x, y1 = a1 * rinv0[mi] * wv.y;
                float y2 = a2 * rinv1[mi] * wv.x, y3 = a3 * rinv1[mi] * wv.y;
                __nv_bfloat16* dh = (seg == 0) ? qhi : khi;
                __nv_bfloat16* dl = (seg == 0) ? qlo : klo;
                uint32_t h, l;
                split_pair(y0, y1, h, l);
                *(uint32_t*)(dh + i0) = h; *(uint32_t*)(dl + i0) = l;
                split_pair(y2, y3, h, l);
                *(uint32_t*)(dh + i1) = h; *(uint32_t*)(dl + i1) = l;
            }
        }
    }
}

// ---------------------------------------------------------------------------
// Tensor-core flash attention (non-causal, scale=1.0), bf16x3 fp32 emulation.
// Grid: (SEQ/128, NHEADS, BATCH). Block 256 = 8 warps, each warp owns 16 q-rows.
// KV block = 32 keys -> 104.4 KB smem -> 2 CTAs/SM for softmax/MMA overlap.
// Epilogue writes z directly as bf16 hi/lo (consumed by GEMM2).
// ---------------------------------------------------------------------------
#define AT_PAD 136                          // bf16 row stride (128 + 8)
#define AT_SMEM ((128 * 2 + 32 * 4) * AT_PAD * 2)   // 104448 bytes

__global__ __launch_bounds__(256, 2)
void attn_mma(const __nv_bfloat16* __restrict__ Qh_g, const __nv_bfloat16* __restrict__ Ql_g,
              const __nv_bfloat16* __restrict__ Kh_g, const __nv_bfloat16* __restrict__ Kl_g,
              const __nv_bfloat16* __restrict__ Vh_g, const __nv_bfloat16* __restrict__ Vl_g,
              __nv_bfloat16* __restrict__ Zh, __nv_bfloat16* __restrict__ Zl)
{
    extern __shared__ __align__(16) __nv_bfloat16 asm_smem[];
    __nv_bfloat16* Qh = asm_smem;
    __nv_bfloat16* Ql = Qh + 128 * AT_PAD;
    __nv_bfloat16* Kh = Ql + 128 * AT_PAD;
    __nv_bfloat16* Kl = Kh + 32 * AT_PAD;
    __nv_bfloat16* Vh = Kl + 32 * AT_PAD;
    __nv_bfloat16* Vl = Vh + 32 * AT_PAD;

    const uint32_t sQh = smem_u32(Qh);
    const uint32_t sQl = smem_u32(Ql);
    const uint32_t sKh = smem_u32(Kh);
    const uint32_t sKl = smem_u32(Kl);
    const uint32_t sVh = smem_u32(Vh);
    const uint32_t sVl = smem_u32(Vl);

    const int tid  = threadIdx.x;
    const int wid  = tid >> 5;
    const int lane = tid & 31;
    const int wm0  = wid * 16;
    const int q0   = blockIdx.x * 128;
    const int h    = blockIdx.y;
    const int b    = blockIdx.z;
    const size_t rowbase = (size_t)b * SEQ;
    const int    hb      = h * DHEAD;

    // Q tile -> smem (hi/lo), reused across all key blocks
#pragma unroll
    for (int i = 0; i < 8; i++) {
        int u = tid + i * 256;              // 0..2047
        int r = u >> 4;
        int c = (u & 15) * 8;
        const size_t g = (rowbase + q0 + r) * D_MODEL + hb + c;
        *(uint4*)(Qh + r * AT_PAD + c) = *(const uint4*)(Qh_g + g);
        *(uint4*)(Ql + r * AT_PAD + c) = *(const uint4*)(Ql_g + g);
    }

    float o[16][4];
#pragma unroll
    for (int ni = 0; ni < 16; ni++)
#pragma unroll
        for (int e = 0; e < 4; e++) o[ni][e] = 0.f;
    float m0 = -1e30f, m1 = -1e30f, l0 = 0.f, l1 = 0.f;

    for (int kb = 0; kb < SEQ / 32; kb++) {
        __syncthreads();                    // previous PV finished reading K/V smem
        const size_t k0g = rowbase + (size_t)kb * 32;
#pragma unroll
        for (int i = 0; i < 2; i++) {
            int u = tid + i * 256;          // 0..511
            int r = u >> 4;                 // 0..31
            int c = (u & 15) * 8;
            const size_t g = (k0g + r) * D_MODEL + hb + c;
            *(uint4*)(Kh + r * AT_PAD + c) = *(const uint4*)(Kh_g + g);
            *(uint4*)(Kl + r * AT_PAD + c) = *(const uint4*)(Kl_g + g);
            *(uint4*)(Vh + r * AT_PAD + c) = *(const uint4*)(Vh_g + g);
            *(uint4*)(Vl + r * AT_PAD + c) = *(const uint4*)(Vl_g + g);
        }
        __syncthreads();

        // ---- S = Q K^T (per warp: 16 x 32), 3-pass emulation ----
        float s[4][4];
#pragma unroll
        for (int j = 0; j < 4; j++)
#pragma unroll
            for (int e = 0; e < 4; e++) s[j][e] = 0.f;

        const uint32_t qoffb = ((wm0 + (lane & 15)) * AT_PAD + (lane >> 4) * 8) * 2;
        const uint32_t krow  = ((lane >> 4) & 1) * 8 + (lane & 7);
        const uint32_t kcolb = ((lane >> 3) & 1) * 8;
#pragma unroll
        for (int ks = 0; ks < 8; ks++) {
            uint32_t ah[4], al[4];
            const uint32_t qoff = qoffb + ks * 32;     // +16 bf16 cols = 32B
            ldsm_x4(ah[0], ah[1], ah[2], ah[3], sQh + qoff);
            ldsm_x4(al[0], al[1], al[2], al[3], sQl + qoff);
#pragma unroll
            for (int np = 0; np < 2; np++) {
                uint32_t bh4[4], bl4[4];
                const uint32_t koff = ((np * 16 + krow) * AT_PAD + ks * 16 + kcolb) * 2;
                ldsm_x4(bh4[0], bh4[1], bh4[2], bh4[3], sKh + koff);
                ldsm_x4(bl4[0], bl4[1], bl4[2], bl4[3], sKl + koff);
                mma16816(s[np * 2],     ah, &bh4[0]);
                mma16816(s[np * 2],     ah, &bl4[0]);
                mma16816(s[np * 2],     al, &bh4[0]);
                mma16816(s[np * 2 + 1], ah, &bh4[2]);
                mma16816(s[np * 2 + 1], ah, &bl4[2]);
                mma16816(s[np * 2 + 1], al, &bh4[2]);
            }
        }

        // ---- online softmax (rows r = lane>>2 and r+8) ----
        float mx0 = -1e30f, mx1 = -1e30f;
#pragma unroll
        for (int j = 0; j < 4; j++) {
            mx0 = fmaxf(mx0, fmaxf(s[j][0], s[j][1]));
            mx1 = fmaxf(mx1, fmaxf(s[j][2], s[j][3]));
        }
        mx0 = fmaxf(mx0, __shfl_xor_sync(0xffffffffu, mx0, 1));
        mx0 = fmaxf(mx0, __shfl_xor_sync(0xffffffffu, mx0, 2));
        mx1 = fmaxf(mx1, __shfl_xor_sync(0xffffffffu, mx1, 1));
        mx1 = fmaxf(mx1, __shfl_xor_sync(0xffffffffu, mx1, 2));
        const float mn0 = fmaxf(m0, mx0);
        const float mn1 = fmaxf(m1, mx1);
        const float c0 = __expf(m0 - mn0);
        const float c1 = __expf(m1 - mn1);
        m0 = mn0; m1 = mn1;
        float rs0 = 0.f, rs1 = 0.f;
#pragma unroll
        for (int j = 0; j < 4; j++) {
            s[j][0] = __expf(s[j][0] - mn0);
            s[j][1] = __expf(s[j][1] - mn0);
            s[j][2] = __expf(s[j][2] - mn1);
            s[j][3] = __expf(s[j][3] - mn1);
            rs0 += s[j][0] + s[j][1];
            rs1 += s[j][2] + s[j][3];
        }
        rs0 += __shfl_xor_sync(0xffffffffu, rs0, 1);
        rs0 += __shfl_xor_sync(0xffffffffu, rs0, 2);
        rs1 += __shfl_xor_sync(0xffffffffu, rs1, 1);
        rs1 += __shfl_xor_sync(0xffffffffu, rs1, 2);
        l0 = l0 * c0 + rs0;
        l1 = l1 * c1 + rs1;
#pragma unroll
        for (int ni = 0; ni < 16; ni++) {
            o[ni][0] *= c0; o[ni][1] *= c0;
            o[ni][2] *= c1; o[ni][3] *= c1;
        }

        // ---- pack P into A-fragments (hi/lo), pure registers ----
        uint32_t ph[2][4], pl[2][4];
#pragma unroll
        for (int t = 0; t < 2; t++) {
            split_pair(s[2 * t][0],     s[2 * t][1],     ph[t][0], pl[t][0]);
            split_pair(s[2 * t][2],     s[2 * t][3],     ph[t][1], pl[t][1]);
            split_pair(s[2 * t + 1][0], s[2 * t + 1][1], ph[t][2], pl[t][2]);
            split_pair(s[2 * t + 1][2], s[2 * t + 1][3], ph[t][3], pl[t][3]);
        }

        // ---- O += P V  (V via ldmatrix.trans; per warp 16 x 128) ----
        const uint32_t vrow  = ((lane >> 3) & 1) * 8 + (lane & 7);
        const uint32_t vcolb = ((lane >> 4) & 1) * 8;
#pragma unroll
        for (int t = 0; t < 2; t++) {
#pragma unroll
            for (int np = 0; np < 8; np++) {
                uint32_t vh4[4], vl4[4];
                const uint32_t voff = ((t * 16 + vrow) * AT_PAD + np * 16 + vcolb) * 2;
                ldsm_x4_t(vh4[0], vh4[1], vh4[2], vh4[3], sVh + voff);
                ldsm_x4_t(vl4[0], vl4[1], vl4[2], vl4[3], sVl + voff);
                mma16816(o[np * 2],     ph[t], &vh4[0]);
                mma16816(o[np * 2],     ph[t], &vl4[0]);
                mma16816(o[np * 2],     pl[t], &vh4[0]);
                mma16816(o[np * 2 + 1], ph[t], &vh4[2]);
                mma16816(o[np * 2 + 1], ph[t], &vl4[2]);
                mma16816(o[np * 2 + 1], pl[t], &vh4[2]);
            }
        }
    }

    // ---- normalize & store Z directly as bf16 hi/lo [b, s, h*dh] ----
    const float inv0 = 1.f / l0, inv1 = 1.f / l1;
    const int r  = lane >> 2;
    const int c2 = (lane & 3) * 2;
    const size_t row0 = rowbase + q0 + wm0 + r;
#pragma unroll
    for (int ni = 0; ni < 16; ni++) {
        const int col = hb + ni * 8 + c2;
        const size_t i0 = row0 * D_MODEL + col;
        const size_t i1 = (row0 + 8) * D_MODEL + col;
        uint32_t hp, lp;
        split_pair(o[ni][0] * inv0, o[ni][1] * inv0, hp, lp);
        *(uint32_t*)(Zh + i0) = hp; *(uint32_t*)(Zl + i0) = lp;
        split_pair(o[ni][2] * inv1, o[ni][3] * inv1, hp, lp);
        *(uint32_t*)(Zh + i1) = hp; *(uint32_t*)(Zl + i1) = lp;
    }
}

// ---------------------------------------------------------------------------
// Launch
// ---------------------------------------------------------------------------
extern "C" void kernel_launch(void* const* d_in, const int* in_sizes, int n_in,
                              void* d_out, int out_size)
{
    const float* x    = (const float*)d_in[0];
    const float* Wqkv = (const float*)d_in[1];
    const float* bqkv = (const float*)d_in[2];
    const float* Wo   = (const float*)d_in[3];
    const float* bo   = (const float*)d_in[4];
    const float* wq   = (const float*)d_in[5];
    const float* wk   = (const float*)d_in[6];

    float* out  = (float*)d_out;
    float* kout = out + (size_t)OUTSZ;       // k_new (pre-norm)
    float* vout = out + (size_t)2 * OUTSZ;   // v_new

    __nv_bfloat16 *ahi, *alo, *bhi, *blo, *qhi, *qlo, *khi, *klo, *vhi, *vlo;
    cudaGetSymbolAddress((void**)&ahi,  g_ahi);
    cudaGetSymbolAddress((void**)&alo,  g_alo);
    cudaGetSymbolAddress((void**)&bhi,  g_bhi);
    cudaGetSymbolAddress((void**)&blo,  g_blo);
    cudaGetSymbolAddress((void**)&qhi,  g_qhi);
    cudaGetSymbolAddress((void**)&qlo,  g_qlo);
    cudaGetSymbolAddress((void**)&khi,  g_khi);
    cudaGetSymbolAddress((void**)&klo,  g_klo);
    cudaGetSymbolAddress((void**)&vhi,  g_vhi);
    cudaGetSymbolAddress((void**)&vlo,  g_vlo);

    cudaFuncSetAttribute(gemm_mma,
                         cudaFuncAttributeMaxDynamicSharedMemorySize, GEMM_SMEM);
    cudaFuncSetAttribute(attn_mma,
                         cudaFuncAttributeMaxDynamicSharedMemorySize, AT_SMEM);

    // 1) split x and Wqkv into bf16 hi/lo
    split_f32<<<OUTSZ / 1024, 256>>>(x, ahi, alo, OUTSZ);
    split_f32<<<(3 * D_MODEL * D_MODEL) / 1024, 256>>>(Wqkv, bhi, blo,
                                                       3 * D_MODEL * D_MODEL);

    // 2) QKV projection with fused RMSNorm+split epilogue:
    //    q -> qhi/qlo, k -> kout fp32 + khi/klo, v -> vout fp32 + vhi/vlo
    gemm_mma<<<dim3(3 * D_MODEL / 128, MTOT / 128), 256, GEMM_SMEM>>>(
        ahi, alo, bhi, blo, bqkv, nullptr, kout, vout, D_MODEL, 1,
        wq, wk, qhi, qlo, khi, klo, vhi, vlo);

    // 3) tensor-core flash attention -> z as bf16 hi/lo (into ahi/alo)
    attn_mma<<<dim3(SEQ / 128, NHEADS, BATCH), 256, AT_SMEM>>>(
        qhi, qlo, khi, klo, vhi, vlo, ahi, alo);

    // 4) split Wo, output projection (plain epilogue)
    split_f32<<<(D_MODEL * D_MODEL) / 1024, 256>>>(Wo, bhi, blo,
                                                   D_MODEL * D_MODEL);
    gemm_mma<<<dim3(D_MODEL / 128, MTOT / 128), 256, GEMM_SMEM>>>(
        ahi, alo, bhi, blo, bo, out, nullptr, nullptr, D_MODEL, 0,
        nullptr, nullptr, nullptr, nullptr, nullptr, nullptr, nullptr, nullptr);
}

// round 17
// speedup vs baseline: 1.0363x; 1.0363x over previous
#include <cuda_runtime.h>
#include <cuda_bf16.h>
#include <cstdint>

// ---------------------------------------------------------------------------
// Problem constants
// ---------------------------------------------------------------------------
#define D_MODEL 2048
#define NHEADS  16
#define DHEAD   128
#define SEQ     2048
#define BATCH   2
#define MTOT    (BATCH * SEQ)        // 4096 rows
#define OUTSZ   (MTOT * D_MODEL)     // 8388608 elements per output tensor

// Scratch buffers (no cudaMalloc allowed -> device globals)
__device__ __nv_bfloat16 g_ahi[MTOT * D_MODEL];   // A-hi (x, then z)
__device__ __nv_bfloat16 g_alo[MTOT * D_MODEL];   // A-lo
__device__ __nv_bfloat16 g_bhi[3 * D_MODEL * D_MODEL]; // B-hi (Wqkv, then Wo)
__device__ __nv_bfloat16 g_blo[3 * D_MODEL * D_MODEL]; // B-lo
__device__ __nv_bfloat16 g_qhi[MTOT * D_MODEL];   // normalized q, hi/lo
__device__ __nv_bfloat16 g_qlo[MTOT * D_MODEL];
__device__ __nv_bfloat16 g_khi[MTOT * D_MODEL];   // normalized k, hi/lo
__device__ __nv_bfloat16 g_klo[MTOT * D_MODEL];
__device__ __nv_bfloat16 g_vhi[MTOT * D_MODEL];   // v, hi/lo
__device__ __nv_bfloat16 g_vlo[MTOT * D_MODEL];

typedef unsigned long long u64;

// ---------------------------------------------------------------------------
// Base-target tensor-core helpers (sm_80+ ISA: ldmatrix / mma.sync / cp.async)
// ---------------------------------------------------------------------------
__device__ __forceinline__ uint32_t smem_u32(const void* p) {
    uint32_t a;
    asm("{ .reg .u64 t; cvta.to.shared.u64 t, %1; cvt.u32.u64 %0, t; }"
        : "=r"(a) : "l"(p));
    return a;
}
__device__ __forceinline__ void ldsm_x4(uint32_t& r0, uint32_t& r1,
                                        uint32_t& r2, uint32_t& r3, uint32_t addr) {
    asm volatile("ldmatrix.sync.aligned.m8n8.x4.shared.b16 {%0,%1,%2,%3}, [%4];"
                 : "=r"(r0), "=r"(r1), "=r"(r2), "=r"(r3) : "r"(addr));
}
__device__ __forceinline__ void ldsm_x4_t(uint32_t& r0, uint32_t& r1,
                                          uint32_t& r2, uint32_t& r3, uint32_t addr) {
    asm volatile("ldmatrix.sync.aligned.m8n8.x4.trans.shared.b16 {%0,%1,%2,%3}, [%4];"
                 : "=r"(r0), "=r"(r1), "=r"(r2), "=r"(r3) : "r"(addr));
}
__device__ __forceinline__ void mma16816(float* d, const uint32_t* a,
                                         const uint32_t* b) {
    asm volatile("mma.sync.aligned.m16n8k16.row.col.f32.bf16.bf16.f32 "
                 "{%0,%1,%2,%3}, {%4,%5,%6,%7}, {%8,%9}, {%0,%1,%2,%3};"
                 : "+f"(d[0]), "+f"(d[1]), "+f"(d[2]), "+f"(d[3])
                 : "r"(a[0]), "r"(a[1]), "r"(a[2]), "r"(a[3]),
                   "r"(b[0]), "r"(b[1]));
}
__device__ __forceinline__ void cp_async16(uint32_t dst, const void* src) {
    asm volatile("cp.async.cg.shared.global [%0], [%1], 16;"
                 :: "r"(dst), "l"(src) : "memory");
}
__device__ __forceinline__ void cp_commit() {
    asm volatile("cp.async.commit_group;" ::: "memory");
}
template <int N>
__device__ __forceinline__ void cp_wait() {
    asm volatile("cp.async.wait_group %0;" :: "n"(N) : "memory");
}
// pack two fp32 -> bf16x2 (x -> low half, y -> high half), round-to-nearest
__device__ __forceinline__ uint32_t bf2pk(float x, float y) {
    uint32_t r;
    asm("cvt.rn.bf16x2.f32 %0, %1, %2;" : "=r"(r) : "f"(y), "f"(x));
    return r;
}
// split pair (p0,p1) into packed hi bf16x2 and packed lo bf16x2
__device__ __forceinline__ void split_pair(float p0, float p1,
                                           uint32_t& hpk, uint32_t& lpk) {
    hpk = bf2pk(p0, p1);
    float h0 = __uint_as_float(hpk << 16);
    float h1 = __uint_as_float(hpk & 0xffff0000u);
    lpk = bf2pk(p0 - h0, p1 - h1);
}

// ---------------------------------------------------------------------------
// fp32 -> (bf16 hi, bf16 lo) split, vectorized
// ---------------------------------------------------------------------------
__global__ __launch_bounds__(256)
void split_f32(const float* __restrict__ src, __nv_bfloat16* __restrict__ hi,
               __nv_bfloat16* __restrict__ lo, int n)
{
    int i = (blockIdx.x * 256 + threadIdx.x) * 4;
    if (i >= n) return;
    float4 x = *(const float4*)(src + i);
    uint32_t h01, l01, h23, l23;
    split_pair(x.x, x.y, h01, l01);
    split_pair(x.z, x.w, h23, l23);
    uint2 hv = {h01, h23}, lv = {l01, l23};
    *(uint2*)(hi + i) = hv;
    *(uint2*)(lo + i) = lv;
}

// ---------------------------------------------------------------------------
// HMMA (mma.sync) GEMM with bf16x3 fp32 emulation.
// mode 0: plain fp32 out (+bias) into out0 (segN width).
// mode 1: QKV-fused epilogue (RMSNorm q/k + hi/lo splits; v split).
// ---------------------------------------------------------------------------
#define GK    2048
#define BK2   32
#define APAD  40
#define PART_ELE (128 * APAD)
#define STAGE_B  (4 * PART_ELE * 2)
#define GEMM_SMEM (2 * STAGE_B)

__global__ __launch_bounds__(256, 2)
void gemm_mma(const __nv_bfloat16* __restrict__ Ahi, const __nv_bfloat16* __restrict__ Alo,
              const __nv_bfloat16* __restrict__ Bhi, const __nv_bfloat16* __restrict__ Blo,
              const float* __restrict__ bias,
              float* __restrict__ out0, float* __restrict__ out1,
              float* __restrict__ out2, int segN, int mode,
              const float* __restrict__ wq, const float* __restrict__ wk,
              __nv_bfloat16* __restrict__ qhi, __nv_bfloat16* __restrict__ qlo,
              __nv_bfloat16* __restrict__ khi, __nv_bfloat16* __restrict__ klo,
              __nv_bfloat16* __restrict__ vhi, __nv_bfloat16* __restrict__ vlo)
{
    extern __shared__ __align__(16) __nv_bfloat16 smem[];
    const uint32_t sb = smem_u32(smem);

    const int tid    = threadIdx.x;
    const int wid    = tid >> 5;
    const int lane   = tid & 31;
    const int warp_m = wid >> 2;
    const int warp_n = wid & 3;
    const int wm0    = warp_m * 64;
    const int wn0    = warp_n * 32;
    const int m0     = blockIdx.y * 128;
    const int n0     = blockIdx.x * 128;

    const __nv_bfloat16* gsrc[4];
    gsrc[0] = Ahi + (size_t)m0 * GK;
    gsrc[1] = Alo + (size_t)m0 * GK;
    gsrc[2] = Bhi + (size_t)n0 * GK;
    gsrc[3] = Blo + (size_t)n0 * GK;

    float acc[4][4][4];
#pragma unroll
    for (int mi = 0; mi < 4; mi++)
#pragma unroll
        for (int ni = 0; ni < 4; ni++)
#pragma unroll
            for (int e = 0; e < 4; e++) acc[mi][ni][e] = 0.f;

    auto load_tile = [&](int t, int buf) {
        const uint32_t sbase = sb + buf * STAGE_B;
#pragma unroll
        for (int p = 0; p < 4; p++) {
            const __nv_bfloat16* s = gsrc[p] + t * BK2;
            const uint32_t dbase = sbase + p * (PART_ELE * 2);
#pragma unroll
            for (int i = 0; i < 2; i++) {
                int idx = tid + i * 256;
                int r   = idx >> 2;
                int c   = (idx & 3) * 8;
                cp_async16(dbase + (r * APAD + c) * 2,
                           s + (size_t)r * GK + c);
            }
        }
        cp_commit();
    };

    load_tile(0, 0);

    const int ntiles = GK / BK2;
    for (int t = 0; t < ntiles; t++) {
        const int buf = t & 1;
        if (t + 1 < ntiles) load_tile(t + 1, buf ^ 1);
        if (t + 1 < ntiles) cp_wait<1>(); else cp_wait<0>();
        __syncthreads();

        const uint32_t aHiB = sb + buf * STAGE_B;
        const uint32_t aLoB = aHiB + PART_ELE * 2;
        const uint32_t bHiB = aHiB + 2 * PART_ELE * 2;
        const uint32_t bLoB = aHiB + 3 * PART_ELE * 2;

#pragma unroll
        for (int ks = 0; ks < 2; ks++) {
            const int brow = wn0 + ((lane >> 4) & 1) * 8 + (lane & 7);
            const int bkof = ks * 16 + ((lane >> 3) & 1) * 8;
            uint32_t bh[2][4], bl[2][4];
#pragma unroll
            for (int ni2 = 0; ni2 < 2; ni2++) {
                const uint32_t boff = ((brow + ni2 * 16) * APAD + bkof) * 2;
                ldsm_x4(bh[ni2][0], bh[ni2][1], bh[ni2][2], bh[ni2][3], bHiB + boff);
                ldsm_x4(bl[ni2][0], bl[ni2][1], bl[ni2][2], bl[ni2][3], bLoB + boff);
            }
            const int arow = wm0 + (lane & 15);
            const int akof = ks * 16 + (lane >> 4) * 8;
#pragma unroll
            for (int mi = 0; mi < 4; mi++) {
                const uint32_t aoff = ((arow + mi * 16) * APAD + akof) * 2;
                uint32_t ah[4], al[4];
                ldsm_x4(ah[0], ah[1], ah[2], ah[3], aHiB + aoff);
                ldsm_x4(al[0], al[1], al[2], al[3], aLoB + aoff);
#pragma unroll
                for (int ni = 0; ni < 4; ni++) {
                    const uint32_t* bhp = &bh[ni >> 1][(ni & 1) * 2];
                    const uint32_t* blp = &bl[ni >> 1][(ni & 1) * 2];
                    mma16816(acc[mi][ni], ah, bhp);
                    mma16816(acc[mi][ni], ah, blp);
                    mma16816(acc[mi][ni], al, bhp);
                }
            }
        }
        __syncthreads();
    }

    // ---- apply bias in-register ----
#pragma unroll
    for (int ni = 0; ni < 4; ni++) {
        const int gn = n0 + wn0 + ni * 8 + (lane & 3) * 2;
        float2 bv = *(const float2*)(bias + gn);
#pragma unroll
        for (int mi = 0; mi < 4; mi++) {
            acc[mi][ni][0] += bv.x; acc[mi][ni][1] += bv.y;
            acc[mi][ni][2] += bv.x; acc[mi][ni][3] += bv.y;
        }
    }

    const int seg = n0 / segN;

    if (mode == 0) {
        float* o = out0;
#pragma unroll
        for (int mi = 0; mi < 4; mi++) {
            const int gm = m0 + wm0 + mi * 16 + (lane >> 2);
#pragma unroll
            for (int ni = 0; ni < 4; ni++) {
                const int cn = n0 + wn0 + ni * 8 + (lane & 3) * 2;
                *(float2*)(o + (size_t)gm * segN + cn)       = *(float2*)&acc[mi][ni][0];
                *(float2*)(o + (size_t)(gm + 8) * segN + cn) = *(float2*)&acc[mi][ni][2];
            }
        }
        return;
    }

    // ---- fused QKV epilogue ----
    float* ssq = (float*)smem;   // [4 warp_n][128 rows]
    float rinv0[4], rinv1[4];

    if (seg < 2) {
#pragma unroll
        for (int mi = 0; mi < 4; mi++) {
            float p0 = 0.f, p1 = 0.f;
#pragma unroll
            for (int ni = 0; ni < 4; ni++) {
                p0 += acc[mi][ni][0] * acc[mi][ni][0] + acc[mi][ni][1] * acc[mi][ni][1];
                p1 += acc[mi][ni][2] * acc[mi][ni][2] + acc[mi][ni][3] * acc[mi][ni][3];
            }
            p0 += __shfl_xor_sync(0xffffffffu, p0, 1);
            p0 += __shfl_xor_sync(0xffffffffu, p0, 2);
            p1 += __shfl_xor_sync(0xffffffffu, p1, 1);
            p1 += __shfl_xor_sync(0xffffffffu, p1, 2);
            if ((lane & 3) == 0) {
                const int rr = wm0 + mi * 16 + (lane >> 2);
                ssq[warp_n * 128 + rr]     = p0;
                ssq[warp_n * 128 + rr + 8] = p1;
            }
        }
        __syncthreads();
#pragma unroll
        for (int mi = 0; mi < 4; mi++) {
            const int rr = wm0 + mi * 16 + (lane >> 2);
            float t0 = ssq[rr] + ssq[128 + rr] + ssq[256 + rr] + ssq[384 + rr];
            float t1 = ssq[rr + 8] + ssq[128 + rr + 8] + ssq[256 + rr + 8] + ssq[384 + rr + 8];
            rinv0[mi] = rsqrtf(t0 * (1.0f / 128.0f) + 1e-6f);
            rinv1[mi] = rsqrtf(t1 * (1.0f / 128.0f) + 1e-6f);
        }
    }

    const int cn = (n0 - seg * segN) + wn0 + (lane & 3) * 2;  // col within 2048 seg
    const int hc = wn0 + (lane & 3) * 2;                      // col within head

#pragma unroll
    for (int mi = 0; mi < 4; mi++) {
        const int gm = m0 + wm0 + mi * 16 + (lane >> 2);
#pragma unroll
        for (int ni = 0; ni < 4; ni++) {
            const int col  = cn + ni * 8;
            const size_t i0 = (size_t)gm * segN + col;
            const size_t i1 = (size_t)(gm + 8) * segN + col;
            float a0 = acc[mi][ni][0], a1 = acc[mi][ni][1];
            float a2 = acc[mi][ni][2], a3 = acc[mi][ni][3];
            if (seg == 2) {
                *(float2*)(out2 + i0) = make_float2(a0, a1);
                *(float2*)(out2 + i1) = make_float2(a2, a3);
                uint32_t h, l;
                split_pair(a0, a1, h, l);
                *(uint32_t*)(vhi + i0) = h; *(uint32_t*)(vlo + i0) = l;
                split_pair(a2, a3, h, l);
                *(uint32_t*)(vhi + i1) = h; *(uint32_t*)(vlo + i1) = l;
            } else {
                const float* wn = (seg == 0) ? wq : wk;
                float2 wv = *(const float2*)(wn + hc + ni * 8);
                if (seg == 1) {
                    *(float2*)(out1 + i0) = make_float2(a0, a1);
                    *(float2*)(out1 + i1) = make_float2(a2, a3);
                }
                float y0 = a0 * rinv0[mi] * wv.x, y1 = a1 * rinv0[mi] * wv.y;
                float y2 = a2 * rinv1[mi] * wv.x, y3 = a3 * rinv1[mi] * wv.y;
                __nv_bfloat16* dh = (seg == 0) ? qhi : khi;
                __nv_bfloat16* dl = (seg == 0) ? qlo : klo;
                uint32_t h, l;
                split_pair(y0, y1, h, l);
                *(uint32_t*)(dh + i0) = h; *(uint32_t*)(dl + i0) = l;
                split_pair(y2, y3, h, l);
                *(uint32_t*)(dh + i1) = h; *(uint32_t*)(dl + i1) = l;
            }
        }
    }
}

// ---------------------------------------------------------------------------
// Tensor-core flash attention (non-causal, scale=1.0), bf16x3 fp32 emulation.
// Grid: (SEQ/128, NHEADS, BATCH). Block 256 = 8 warps, each warp owns 16 q-rows.
// KV block = 32 keys, 104.4 KB smem, 2 CTAs/SM.
// NEW: cp.async software pipeline — K(n+1) loads overlap softmax+PV(n),
// V(n+1) loads overlap S(n+1). Single K buffer + single V buffer; each
// __syncthreads doubles as "buffer free" + "async data visible" fence.
// ---------------------------------------------------------------------------
#define AT_PAD 136                          // bf16 row stride (128 + 8)
#define AT_SMEM ((128 * 2 + 32 * 4) * AT_PAD * 2)   // 104448 bytes
#define NKB (SEQ / 32)

__global__ __launch_bounds__(256, 2)
void attn_mma(const __nv_bfloat16* __restrict__ Qh_g, const __nv_bfloat16* __restrict__ Ql_g,
              const __nv_bfloat16* __restrict__ Kh_g, const __nv_bfloat16* __restrict__ Kl_g,
              const __nv_bfloat16* __restrict__ Vh_g, const __nv_bfloat16* __restrict__ Vl_g,
              __nv_bfloat16* __restrict__ Zh, __nv_bfloat16* __restrict__ Zl)
{
    extern __shared__ __align__(16) __nv_bfloat16 asm_smem[];
    __nv_bfloat16* Qh = asm_smem;
    __nv_bfloat16* Ql = Qh + 128 * AT_PAD;
    __nv_bfloat16* Kh = Ql + 128 * AT_PAD;
    __nv_bfloat16* Kl = Kh + 32 * AT_PAD;
    __nv_bfloat16* Vh = Kl + 32 * AT_PAD;
    __nv_bfloat16* Vl = Vh + 32 * AT_PAD;

    const uint32_t sQh = smem_u32(Qh);
    const uint32_t sQl = smem_u32(Ql);
    const uint32_t sKh = smem_u32(Kh);
    const uint32_t sKl = smem_u32(Kl);
    const uint32_t sVh = smem_u32(Vh);
    const uint32_t sVl = smem_u32(Vl);

    const int tid  = threadIdx.x;
    const int wid  = tid >> 5;
    const int lane = tid & 31;
    const int wm0  = wid * 16;
    const int q0   = blockIdx.x * 128;
    const int h    = blockIdx.y;
    const int b    = blockIdx.z;
    const size_t rowbase = (size_t)b * SEQ;
    const int    hb      = h * DHEAD;

    // per-thread load coordinates (16B granularity)
    const int lr0 = tid >> 4;            // 0..15
    const int lc  = (tid & 15) * 8;

    auto issue_K = [&](int kb) {
        const size_t k0g = rowbase + (size_t)kb * 32;
#pragma unroll
        for (int i = 0; i < 2; i++) {
            int r = lr0 + i * 16;                    // 0..31
            const size_t g = (k0g + r) * D_MODEL + hb + lc;
            const uint32_t so = (r * AT_PAD + lc) * 2;
            cp_async16(sKh + so, Kh_g + g);
            cp_async16(sKl + so, Kl_g + g);
        }
        cp_commit();
    };
    auto issue_V = [&](int kb) {
        const size_t k0g = rowbase + (size_t)kb * 32;
#pragma unroll
        for (int i = 0; i < 2; i++) {
            int r = lr0 + i * 16;
            const size_t g = (k0g + r) * D_MODEL + hb + lc;
            const uint32_t so = (r * AT_PAD + lc) * 2;
            cp_async16(sVh + so, Vh_g + g);
            cp_async16(sVl + so, Vl_g + g);
        }
        cp_commit();
    };

    // prologue: Q tile (group 0), K0 (group 1), V0 (group 2)
#pragma unroll
    for (int i = 0; i < 8; i++) {
        int r = lr0 + i * 16;                        // 0..127
        const size_t g = (rowbase + q0 + r) * D_MODEL + hb + lc;
        const uint32_t so = (r * AT_PAD + lc) * 2;
        cp_async16(sQh + so, Qh_g + g);
        cp_async16(sQl + so, Ql_g + g);
    }
    cp_commit();
    issue_K(0);
    issue_V(0);
    cp_wait<1>();          // Q + K0 done (V0 may be in flight)
    __syncthreads();       // Q, K0 visible to all warps

    float o[16][4];
#pragma unroll
    for (int ni = 0; ni < 16; ni++)
#pragma unroll
        for (int e = 0; e < 4; e++) o[ni][e] = 0.f;
    float m0 = -1e30f, m1 = -1e30f, l0 = 0.f, l1 = 0.f;

    const uint32_t qoffb = ((wm0 + (lane & 15)) * AT_PAD + (lane >> 4) * 8) * 2;
    const uint32_t krow  = ((lane >> 4) & 1) * 8 + (lane & 7);
    const uint32_t kcolb = ((lane >> 3) & 1) * 8;
    const uint32_t vrow  = ((lane >> 3) & 1) * 8 + (lane & 7);
    const uint32_t vcolb = ((lane >> 4) & 1) * 8;

    for (int kb = 0; kb < NKB; kb++) {
        // ---- S = Q K^T (per warp: 16 x 32), 3-pass emulation ----
        float s[4][4];
#pragma unroll
        for (int j = 0; j < 4; j++)
#pragma unroll
            for (int e = 0; e < 4; e++) s[j][e] = 0.f;

#pragma unroll
        for (int ks = 0; ks < 8; ks++) {
            uint32_t ah[4], al[4];
            const uint32_t qoff = qoffb + ks * 32;     // +16 bf16 cols = 32B
            ldsm_x4(ah[0], ah[1], ah[2], ah[3], sQh + qoff);
            ldsm_x4(al[0], al[1], al[2], al[3], sQl + qoff);
#pragma unroll
            for (int np = 0; np < 2; np++) {
                uint32_t bh4[4], bl4[4];
                const uint32_t koff = ((np * 16 + krow) * AT_PAD + ks * 16 + kcolb) * 2;
                ldsm_x4(bh4[0], bh4[1], bh4[2], bh4[3], sKh + koff);
                ldsm_x4(bl4[0], bl4[1], bl4[2], bl4[3], sKl + koff);
                mma16816(s[np * 2],     ah, &bh4[0]);
                mma16816(s[np * 2],     ah, &bl4[0]);
                mma16816(s[np * 2],     al, &bh4[0]);
                mma16816(s[np * 2 + 1], ah, &bh4[2]);
                mma16816(s[np * 2 + 1], ah, &bl4[2]);
                mma16816(s[np * 2 + 1], al, &bh4[2]);
            }
        }

        // K buffer free from here; V(kb) must be resident for PV below.
        cp_wait<0>();          // V(kb) arrived (issued one iteration ago)
        __syncthreads();       // all warps done with K; V data visible
        if (kb + 1 < NKB) issue_K(kb + 1);   // overlaps softmax + PV

        // ---- online softmax (rows r = lane>>2 and r+8) ----
        float mx0 = -1e30f, mx1 = -1e30f;
#pragma unroll
        for (int j = 0; j < 4; j++) {
            mx0 = fmaxf(mx0, fmaxf(s[j][0], s[j][1]));
            mx1 = fmaxf(mx1, fmaxf(s[j][2], s[j][3]));
        }
        mx0 = fmaxf(mx0, __shfl_xor_sync(0xffffffffu, mx0, 1));
        mx0 = fmaxf(mx0, __shfl_xor_sync(0xffffffffu, mx0, 2));
        mx1 = fmaxf(mx1, __shfl_xor_sync(0xffffffffu, mx1, 1));
        mx1 = fmaxf(mx1, __shfl_xor_sync(0xffffffffu, mx1, 2));
        const float mn0 = fmaxf(m0, mx0);
        const float mn1 = fmaxf(m1, mx1);
        const float c0 = __expf(m0 - mn0);
        const float c1 = __expf(m1 - mn1);
        m0 = mn0; m1 = mn1;
        float rs0 = 0.f, rs1 = 0.f;
#pragma unroll
        for (int j = 0; j < 4; j++) {
            s[j][0] = __expf(s[j][0] - mn0);
            s[j][1] = __expf(s[j][1] - mn0);
            s[j][2] = __expf(s[j][2] - mn1);
            s[j][3] = __expf(s[j][3] - mn1);
            rs0 += s[j][0] + s[j][1];
            rs1 += s[j][2] + s[j][3];
        }
        rs0 += __shfl_xor_sync(0xffffffffu, rs0, 1);
        rs0 += __shfl_xor_sync(0xffffffffu, rs0, 2);
        rs1 += __shfl_xor_sync(0xffffffffu, rs1, 1);
        rs1 += __shfl_xor_sync(0xffffffffu, rs1, 2);
        l0 = l0 * c0 + rs0;
        l1 = l1 * c1 + rs1;
#pragma unroll
        for (int ni = 0; ni < 16; ni++) {
            o[ni][0] *= c0; o[ni][1] *= c0;
            o[ni][2] *= c1; o[ni][3] *= c1;
        }

        // ---- pack P into A-fragments (hi/lo), pure registers ----
        uint32_t ph[2][4], pl[2][4];
#pragma unroll
        for (int t = 0; t < 2; t++) {
            split_pair(s[2 * t][0],     s[2 * t][1],     ph[t][0], pl[t][0]);
            split_pair(s[2 * t][2],     s[2 * t][3],     ph[t][1], pl[t][1]);
            split_pair(s[2 * t + 1][0], s[2 * t + 1][1], ph[t][2], pl[t][2]);
            split_pair(s[2 * t + 1][2], s[2 * t + 1][3], ph[t][3], pl[t][3]);
        }

        // ---- O += P V  (V via ldmatrix.trans; per warp 16 x 128) ----
#pragma unroll
        for (int t = 0; t < 2; t++) {
#pragma unroll
            for (int np = 0; np < 8; np++) {
                uint32_t vh4[4], vl4[4];
                const uint32_t voff = ((t * 16 + vrow) * AT_PAD + np * 16 + vcolb) * 2;
                ldsm_x4_t(vh4[0], vh4[1], vh4[2], vh4[3], sVh + voff);
                ldsm_x4_t(vl4[0], vl4[1], vl4[2], vl4[3], sVl + voff);
                mma16816(o[np * 2],     ph[t], &vh4[0]);
                mma16816(o[np * 2],     ph[t], &vl4[0]);
                mma16816(o[np * 2],     pl[t], &vh4[0]);
                mma16816(o[np * 2 + 1], ph[t], &vh4[2]);
                mma16816(o[np * 2 + 1], ph[t], &vl4[2]);
                mma16816(o[np * 2 + 1], pl[t], &vh4[2]);
            }
        }

        // V buffer free; K(kb+1) must be resident for next S.
        cp_wait<0>();          // K(kb+1) arrived (issued above, pre-softmax)
        __syncthreads();       // all warps done with V; K(kb+1) data visible
        if (kb + 1 < NKB) issue_V(kb + 1);   // overlaps S(kb+1)
    }

    // ---- normalize & store Z directly as bf16 hi/lo [b, s, h*dh] ----
    const float inv0 = 1.f / l0, inv1 = 1.f / l1;
    const int r  = lane >> 2;
    const int c2 = (lane & 3) * 2;
    const size_t row0 = rowbase + q0 + wm0 + r;
#pragma unroll
    for (int ni = 0; ni < 16; ni++) {
        const int col = hb + ni * 8 + c2;
        const size_t i0 = row0 * D_MODEL + col;
        const size_t i1 = (row0 + 8) * D_MODEL + col;
        uint32_t hp, lp;
        split_pair(o[ni][0] * inv0, o[ni][1] * inv0, hp, lp);
        *(uint32_t*)(Zh + i0) = hp; *(uint32_t*)(Zl + i0) = lp;
        split_pair(o[ni][2] * inv1, o[ni][3] * inv1, hp, lp);
        *(uint32_t*)(Zh + i1) = hp; *(uint32_t*)(Zl + i1) = lp;
    }
}

// ---------------------------------------------------------------------------
// Launch
// ---------------------------------------------------------------------------
extern "C" void kernel_launch(void* const* d_in, const int* in_sizes, int n_in,
                              void* d_out, int out_size)
{
    const float* x    = (const float*)d_in[0];
    const float* Wqkv = (const float*)d_in[1];
    const float* bqkv = (const float*)d_in[2];
    const float* Wo   = (const float*)d_in[3];
    const float* bo   = (const float*)d_in[4];
    const float* wq   = (const float*)d_in[5];
    const float* wk   = (const float*)d_in[6];

    float* out  = (float*)d_out;
    float* kout = out + (size_t)OUTSZ;       // k_new (pre-norm)
    float* vout = out + (size_t)2 * OUTSZ;   // v_new

    __nv_bfloat16 *ahi, *alo, *bhi, *blo, *qhi, *qlo, *khi, *klo, *vhi, *vlo;
    cudaGetSymbolAddress((void**)&ahi,  g_ahi);
    cudaGetSymbolAddress((void**)&alo,  g_alo);
    cudaGetSymbolAddress((void**)&bhi,  g_bhi);
    cudaGetSymbolAddress((void**)&blo,  g_blo);
    cudaGetSymbolAddress((void**)&qhi,  g_qhi);
    cudaGetSymbolAddress((void**)&qlo,  g_qlo);
    cudaGetSymbolAddress((void**)&khi,  g_khi);
    cudaGetSymbolAddress((void**)&klo,  g_klo);
    cudaGetSymbolAddress((void**)&vhi,  g_vhi);
    cudaGetSymbolAddress((void**)&vlo,  g_vlo);

    cudaFuncSetAttribute(gemm_mma,
                         cudaFuncAttributeMaxDynamicSharedMemorySize, GEMM_SMEM);
    cudaFuncSetAttribute(attn_mma,
                         cudaFuncAttributeMaxDynamicSharedMemorySize, AT_SMEM);

    // 1) split x and Wqkv into bf16 hi/lo
    split_f32<<<OUTSZ / 1024, 256>>>(x, ahi, alo, OUTSZ);
    split_f32<<<(3 * D_MODEL * D_MODEL) / 1024, 256>>>(Wqkv, bhi, blo,
                                                       3 * D_MODEL * D_MODEL);

    // 2) QKV projection with fused RMSNorm+split epilogue:
    //    q -> qhi/qlo, k -> kout fp32 + khi/klo, v -> vout fp32 + vhi/vlo
    gemm_mma<<<dim3(3 * D_MODEL / 128, MTOT / 128), 256, GEMM_SMEM>>>(
        ahi, alo, bhi, blo, bqkv, nullptr, kout, vout, D_MODEL, 1,
        wq, wk, qhi, qlo, khi, klo, vhi, vlo);

    // 3) tensor-core flash attention -> z as bf16 hi/lo (into ahi/alo)
    attn_mma<<<dim3(SEQ / 128, NHEADS, BATCH), 256, AT_SMEM>>>(
        qhi, qlo, khi, klo, vhi, vlo, ahi, alo);

    // 4) split Wo, output projection (plain epilogue)
    split_f32<<<(D_MODEL * D_MODEL) / 1024, 256>>>(Wo, bhi, blo,
                                                   D_MODEL * D_MODEL);
    gemm_mma<<<dim3(D_MODEL / 128, MTOT / 128), 256, GEMM_SMEM>>>(
        ahi, alo, bhi, blo, bo, out, nullptr, nullptr, D_MODEL, 0,
        nullptr, nullptr, nullptr, nullptr, nullptr, nullptr, nullptr, nullptr);
}